// round 1
// baseline (speedup 1.0000x reference)
#include <cuda_runtime.h>

#define INV_SQRT2 0.70710678118654752440f

// Inter-level lowpass scratch, planar layout: [tree][b][c][H][W]
__device__ float g_lo1[4 * 8 * 3 * 256 * 256];  // after level 1 (256x256)
__device__ float g_lo2[4 * 8 * 3 * 128 * 128];  // after level 2 (128x128)

// Fused 2D analysis filter bank for one level, all 4 dual trees.
//   out[n] = sum_s f[s] * x[(2n - s + 5) mod N]   (per axis, circular)
// SHARED=true: single NHWC input (level 1, channel stride 3), only 2 distinct
// row-pass results (per row-tree m). SHARED=false: 4 planar per-tree inputs.
template <int TI, int TJ, bool SHARED>
__global__ __launch_bounds__(256) void afb_kernel(
    const float* __restrict__ in_base,
    long long tree_stride,            // elements between tree planes (ignored if SHARED)
    int Hin,                          // input spatial size (square)
    const float* __restrict__ filt,   // [2][2][10]: [tree m/n][lo,hi][tap]
    float scale,                      // 0.5 at level 1, 1.0 otherwise
    int levelj,                       // 0,1,2 -> subband size 256>>levelj
    float* __restrict__ lo_out,       // planar per-tree lowpass out, or null if final
    float* __restrict__ out)          // final output (8,1024,1024,3)
{
    const int Win  = Hin;
    const int Hout = Hin >> 1;
    const int Wout = Hout;
    constexpr int PR = 2 * TI + 8;
    constexpr int PC = 2 * TJ + 8;
    constexpr int NSLOT = SHARED ? 1 : 4;
    constexpr int NR    = SHARED ? 2 : 4;

    extern __shared__ float smem[];
    float* s_fr  = smem;                       // 40 reversed filter taps (pad 48)
    float* s_in  = smem + 48;                  // NSLOT * PR * PC
    float* s_row = s_in + NSLOT * PR * PC;     // NR * 2 * TI * PC

    const int tid = threadIdx.x;
    const int b   = blockIdx.z;
    const int c   = blockIdx.y;
    const int tilesW = Wout / TJ;
    const int i0 = (blockIdx.x / tilesW) * TI;
    const int j0 = (blockIdx.x % tilesW) * TJ;

    // Reversed filters: fr[g][u] = f[g][9-u]
    if (tid < 40) {
        int g = tid / 10, u = tid % 10;
        s_fr[g * 10 + u] = filt[g * 10 + (9 - u)];
    }

    // ---- Load input patch(es), circular indexing ----
    const int g0r = 2 * i0 - 4;
    const int g0c = 2 * j0 - 4;
    for (int idx = tid; idx < NSLOT * PR * PC; idx += 256) {
        int slot = idx / (PR * PC);
        int rem  = idx % (PR * PC);
        int pr = rem / PC, pc = rem % PC;
        int h = g0r + pr; if (h < 0) h += Hin; if (h >= Hin) h -= Hin;
        int w = g0c + pc; if (w < 0) w += Win; if (w >= Win) w -= Win;
        float v;
        if (SHARED) {
            // NHWC, channel stride 3
            v = in_base[(((long long)b * Hin + h) * Win + w) * 3 + c];
        } else {
            v = in_base[(long long)slot * tree_stride +
                        (((long long)b * 3 + c) * Hin + h) * (long long)Win + w];
        }
        s_in[idx] = v * scale;
    }
    __syncthreads();

    // ---- Row pass: rowres[r][lh][i][pc] = sum_u fr[m][lh][u] * patch[2i+u][pc] ----
    for (int idx = tid; idx < NR * 2 * TI * PC; idx += 256) {
        int pc = idx % PC;
        int t2 = idx / PC;
        int i  = t2 % TI; t2 /= TI;
        int lh = t2 % 2;
        int r  = t2 / 2;
        int m    = SHARED ? r : (r >> 1);
        int slot = SHARED ? 0 : r;
        const float* fr  = s_fr + (m * 2 + lh) * 10;
        const float* pin = s_in + slot * (PR * PC) + (2 * i) * PC + pc;
        float acc = 0.f;
        #pragma unroll
        for (int u = 0; u < 10; u++) acc += fr[u] * pin[u * PC];
        s_row[idx] = acc;
    }
    __syncthreads();

    // ---- Col pass + dual-tree combine + scatter ----
    const int S = 256 >> levelj;   // subband size at this level
    for (int pos = tid; pos < TI * TJ; pos += 256) {
        int i = pos / TJ, j = pos % TJ;
        float vLL[4];
        float v[3][4];   // [LH,HL,HH][tree]
        #pragma unroll
        for (int t = 0; t < 4; t++) {
            int m = t >> 1, n = t & 1;
            int rr = SHARED ? m : t;
            const float* Rlo = s_row + ((rr * 2 + 0) * TI + i) * PC + 2 * j;
            const float* Rhi = s_row + ((rr * 2 + 1) * TI + i) * PC + 2 * j;
            const float* flo = s_fr + (n * 2 + 0) * 10;
            const float* fhi = s_fr + (n * 2 + 1) * 10;
            float ll = 0.f, lh = 0.f, hl = 0.f, hh = 0.f;
            #pragma unroll
            for (int u = 0; u < 10; u++) {
                float rl = Rlo[u], rh = Rhi[u];
                ll += flo[u] * rl;
                lh += fhi[u] * rl;
                hl += flo[u] * rh;
                hh += fhi[u] * rh;
            }
            vLL[t] = ll; v[0][t] = lh; v[1][t] = hl; v[2][t] = hh;
        }
        const int oi = i0 + i, oj = j0 + j;
        // Lowpass
        if (lo_out) {
            #pragma unroll
            for (int t = 0; t < 4; t++)
                lo_out[(((long long)t * 8 + b) * 3 + c) * (long long)Hout * Wout +
                       (long long)oi * Wout + oj] = vLL[t];
        } else {
            // final level: raw lowpass at tile(m,n), offset (0,0), size 64
            #pragma unroll
            for (int t = 0; t < 4; t++) {
                int m = t >> 1, n = t & 1;
                long long R = 512LL * m + oi, C = 512LL * n + oj;
                out[(((long long)b * 1024 + R) * 1024 + C) * 3 + c] = vLL[t];
            }
        }
        // Subbands: s0=LH @(0,S), s1=HL @(S,0), s2=HH @(S,S) within each tile.
        // combine: tile(0,0)=(t00+t11)/r2, tile(1,1)=(t00-t11)/r2,
        //          tile(0,1)=(t01+t10)/r2, tile(1,0)=(t01-t10)/r2
        #pragma unroll
        for (int s = 0; s < 3; s++) {
            int ro = (s == 0) ? 0 : S;
            int co = (s == 1) ? 0 : S;
            float p00 = (v[s][0] + v[s][3]) * INV_SQRT2;
            float p11 = (v[s][0] - v[s][3]) * INV_SQRT2;
            float p01 = (v[s][1] + v[s][2]) * INV_SQRT2;
            float p10 = (v[s][1] - v[s][2]) * INV_SQRT2;
            long long Rb = ro + oi, Cb = co + oj;
            long long rowA = ((long long)b * 1024 + Rb) * 1024;
            long long rowB = ((long long)b * 1024 + 512 + Rb) * 1024;
            out[(rowA + Cb)       * 3 + c] = p00;
            out[(rowA + 512 + Cb) * 3 + c] = p01;
            out[(rowB + Cb)       * 3 + c] = p10;
            out[(rowB + 512 + Cb) * 3 + c] = p11;
        }
    }
}

extern "C" void kernel_launch(void* const* d_in, const int* in_sizes, int n_in,
                              void* d_out, int out_size)
{
    const float* x   = (const float*)d_in[0];
    const float* Faf = (const float*)d_in[1];
    const float* af  = (const float*)d_in[2];
    float* out = (float*)d_out;

    float *lo1, *lo2;
    cudaGetSymbolAddress((void**)&lo1, g_lo1);
    cudaGetSymbolAddress((void**)&lo2, g_lo2);

    // Level 1: in x (512, NHWC shared), out subbands (256) + lo1
    {
        dim3 grid((256 / 16) * (256 / 32), 3, 8);
        size_t smem = (48 + 1 * 40 * 72 + 2 * 2 * 16 * 72) * sizeof(float); // 30144 B
        afb_kernel<16, 32, true><<<grid, 256, smem>>>(
            x, 0, 512, Faf, 0.5f, 0, lo1, out);
    }
    // Level 2: in lo1 (256, planar per-tree), out subbands (128) + lo2
    {
        dim3 grid((128 / 16) * (128 / 16), 3, 8);
        size_t smem = (48 + 4 * 40 * 40 + 4 * 2 * 16 * 40) * sizeof(float); // 46272 B
        afb_kernel<16, 16, false><<<grid, 256, smem>>>(
            lo1, (long long)8 * 3 * 256 * 256, 256, af, 1.0f, 1, lo2, out);
    }
    // Level 3: in lo2 (128), out subbands (64) + raw lowpass into out
    {
        dim3 grid((64 / 16) * (64 / 16), 3, 8);
        size_t smem = (48 + 4 * 40 * 40 + 4 * 2 * 16 * 40) * sizeof(float); // 46272 B
        afb_kernel<16, 16, false><<<grid, 256, smem>>>(
            lo2, (long long)8 * 3 * 128 * 128, 128, af, 1.0f, 2, nullptr, out);
    }
}